// round 1
// baseline (speedup 1.0000x reference)
#include <cuda_runtime.h>

#define B_    4
#define N_    2048
#define INF_  512
#define D_    64
#define H_    8
#define BH_   32

// ---------------- scratch (device globals; no allocation) ----------------
__device__ __align__(16) float g_V[B_ * N_ * D_];            // (b, n, 64)
__device__ float g_Q[BH_ * N_];                              // (b*8+h, n)
__device__ float g_K[BH_ * N_];
__device__ float g_sq[BH_ * N_];                             // sorted Q values
__device__ int   g_si[BH_ * N_];                             // sorted index
__device__ float g_e1[BH_ * N_];                             // exp(Qsorted)
__device__ float g_e2[BH_ * N_];                             // exp(0.01*Qsorted)
__device__ float g_pe1[BH_ * (N_ + 1)];                      // exclusive scalar prefix of e1
__device__ float g_pe2[BH_ * (N_ + 1)];
__device__ int   g_t[BH_ * N_];                              // rank t_i per output row
__device__ float g_cstart[BH_ * 16 * D_ * 2];                // chunk-start running sums (P,N)
__device__ __align__(16) float g_cum[(size_t)BH_ * (N_ + 1) * D_ * 2]; // interleaved (P,N) per f

// ---------------- Kernel A: V = X@Wv + bv, then Q,K projections ----------
__global__ void __launch_bounds__(256) kernelA(
    const float* __restrict__ X,  const float* __restrict__ Wv, const float* __restrict__ bv,
    const float* __restrict__ Wq, const float* __restrict__ bq,
    const float* __restrict__ Wk, const float* __restrict__ bk)
{
    __shared__ float Xs[64][33];
    __shared__ __align__(16) float Ws[32][64];
    __shared__ float Vs[64][65];

    int tid = threadIdx.x;
    int tx = tid & 15, ty = tid >> 4;
    int row0 = blockIdx.x * 64;                 // global row over b*N_

    float acc[4][4] = {};

    for (int kt = 0; kt < INF_; kt += 32) {
        for (int idx = tid; idx < 64 * 32; idx += 256) {
            int r = idx >> 5, kk = idx & 31;
            Xs[r][kk] = X[(size_t)(row0 + r) * INF_ + kt + kk];
        }
        for (int idx = tid; idx < 32 * 64; idx += 256) {
            int kk = idx >> 6, c = idx & 63;
            Ws[kk][c] = Wv[(kt + kk) * 64 + c];
        }
        __syncthreads();
#pragma unroll
        for (int kk = 0; kk < 32; ++kk) {
            float a0 = Xs[ty * 4 + 0][kk];
            float a1 = Xs[ty * 4 + 1][kk];
            float a2 = Xs[ty * 4 + 2][kk];
            float a3 = Xs[ty * 4 + 3][kk];
            float4 bb = *(const float4*)&Ws[kk][tx * 4];
            acc[0][0] += a0 * bb.x; acc[0][1] += a0 * bb.y; acc[0][2] += a0 * bb.z; acc[0][3] += a0 * bb.w;
            acc[1][0] += a1 * bb.x; acc[1][1] += a1 * bb.y; acc[1][2] += a1 * bb.z; acc[1][3] += a1 * bb.w;
            acc[2][0] += a2 * bb.x; acc[2][1] += a2 * bb.y; acc[2][2] += a2 * bb.z; acc[2][3] += a2 * bb.w;
            acc[3][0] += a3 * bb.x; acc[3][1] += a3 * bb.y; acc[3][2] += a3 * bb.z; acc[3][3] += a3 * bb.w;
        }
        __syncthreads();
    }

    float b0 = bv[tx * 4 + 0], b1 = bv[tx * 4 + 1], b2 = bv[tx * 4 + 2], b3 = bv[tx * 4 + 3];
#pragma unroll
    for (int i = 0; i < 4; ++i) {
        Vs[ty * 4 + i][tx * 4 + 0] = acc[i][0] + b0;
        Vs[ty * 4 + i][tx * 4 + 1] = acc[i][1] + b1;
        Vs[ty * 4 + i][tx * 4 + 2] = acc[i][2] + b2;
        Vs[ty * 4 + i][tx * 4 + 3] = acc[i][3] + b3;
    }
    __syncthreads();

    // write V
#pragma unroll
    for (int i = 0; i < 4; ++i) {
        float4 v = make_float4(Vs[ty * 4 + i][tx * 4 + 0], Vs[ty * 4 + i][tx * 4 + 1],
                               Vs[ty * 4 + i][tx * 4 + 2], Vs[ty * 4 + i][tx * 4 + 3]);
        *(float4*)&g_V[(size_t)(row0 + ty * 4 + i) * 64 + tx * 4] = v;
    }

    // Q, K projections: 64 rows x 8 heads; each thread does 2 heads of 1 row
    int bb_ = row0 >> 11;               // batch
    int n0  = row0 & (N_ - 1);
    int r   = tid >> 2;
    int hp  = (tid & 3) * 2;
    float q0 = bq[hp], q1 = bq[hp + 1];
    float k0 = bk[hp], k1 = bk[hp + 1];
#pragma unroll 8
    for (int f = 0; f < 64; ++f) {
        float v = Vs[r][f];
        q0 += v * Wq[f * 8 + hp]; q1 += v * Wq[f * 8 + hp + 1];
        k0 += v * Wk[f * 8 + hp]; k1 += v * Wk[f * 8 + hp + 1];
    }
    int n = n0 + r;
    g_Q[(bb_ * 8 + hp) * N_ + n]     = q0;
    g_Q[(bb_ * 8 + hp + 1) * N_ + n] = q1;
    g_K[(bb_ * 8 + hp) * N_ + n]     = k0;
    g_K[(bb_ * 8 + hp + 1) * N_ + n] = k1;
}

// ------------- Kernel B1: per (b,h) sort + scans + ranks ------------------
__global__ void __launch_bounds__(1024) kernelB1()
{
    int bh = blockIdx.x;
    int b  = bh >> 3;
    int tid = threadIdx.x;

    __shared__ float sv[N_];
    __shared__ int   si[N_];
    __shared__ float e1[N_], e2[N_];
    __shared__ float partP[16][64], partN[16][64];
    __shared__ float c1[128], c2[128];

    for (int r = tid; r < N_; r += 1024) { sv[r] = g_Q[bh * N_ + r]; si[r] = r; }
    __syncthreads();

    // bitonic sort ascending (2048 elems, 1024 compare threads)
    for (int k = 2; k <= N_; k <<= 1) {
        for (int j = k >> 1; j > 0; j >>= 1) {
            int i = ((tid & ~(j - 1)) << 1) | (tid & (j - 1));
            int p = i | j;
            bool up = (i & k) == 0;
            float a = sv[i], c = sv[p];
            if ((a > c) == up) {
                sv[i] = c; sv[p] = a;
                int t = si[i]; si[i] = si[p]; si[p] = t;
            }
            __syncthreads();
        }
    }

    for (int r = tid; r < N_; r += 1024) {
        float q = sv[r];
        float x1 = __expf(q), x2 = __expf(0.01f * q);
        e1[r] = x1; e2[r] = x2;
        g_sq[bh * N_ + r] = q;
        g_si[bh * N_ + r] = si[r];
        g_e1[bh * N_ + r] = x1;
        g_e2[bh * N_ + r] = x2;
    }
    __syncthreads();

    // rank t_i = #{r : Qsorted[r] <= -K_i}  (smem binary search)
    for (int i = tid; i < N_; i += 1024) {
        float th = -g_K[bh * N_ + i];
        int lo = 0, hi = N_;
        while (lo < hi) {
            int mid = (lo + hi) >> 1;
            if (sv[mid] <= th) lo = mid + 1; else hi = mid;
        }
        g_t[bh * N_ + i] = lo;
    }

    // chunk partial vector sums: f = tid&63, g = tid>>6, chunk = 128 rows
    int f = tid & 63, g = tid >> 6;
    float accP = 0.f, accN = 0.f;
    for (int r = g * 128; r < g * 128 + 128; ++r) {
        float v = g_V[((size_t)b * N_ + si[r]) * 64 + f];
        accP += e1[r] * v;
        accN += e2[r] * v;
    }
    partP[g][f] = accP; partN[g][f] = accN;
    __syncthreads();

    if (tid < 64) {
        float run = 0.f;
        for (int gg = 0; gg < 16; ++gg) {
            float t = partP[gg][tid];
            g_cstart[((bh * 16 + gg) * 64 + tid) * 2 + 0] = run;
            run += t;
        }
        g_cum[((size_t)bh * (N_ + 1) + N_) * 128 + tid * 2 + 0] = run;   // column total (P)
    } else if (tid < 128) {
        int ff = tid - 64;
        float run = 0.f;
        for (int gg = 0; gg < 16; ++gg) {
            float t = partN[gg][ff];
            g_cstart[((bh * 16 + gg) * 64 + ff) * 2 + 1] = run;
            run += t;
        }
        g_cum[((size_t)bh * (N_ + 1) + N_) * 128 + ff * 2 + 1] = run;    // column total (N)
    }

    // scalar exclusive scans of e1, e2 (chunked: 128 chunks of 16)
    if (tid < 128) {
        float s1 = 0.f, s2 = 0.f;
        for (int q = 0; q < 16; ++q) { s1 += e1[tid * 16 + q]; s2 += e2[tid * 16 + q]; }
        c1[tid] = s1; c2[tid] = s2;
    }
    __syncthreads();
    if (tid == 0) {
        float r1 = 0.f, r2 = 0.f;
        for (int q = 0; q < 128; ++q) {
            float t1 = c1[q], t2 = c2[q];
            c1[q] = r1; c2[q] = r2;
            r1 += t1; r2 += t2;
        }
        g_pe1[bh * (N_ + 1) + N_] = r1;
        g_pe2[bh * (N_ + 1) + N_] = r2;
    }
    __syncthreads();
    if (tid < 128) {
        float r1 = c1[tid], r2 = c2[tid];
        for (int q = 0; q < 16; ++q) {
            int r = tid * 16 + q;
            g_pe1[bh * (N_ + 1) + r] = r1;
            g_pe2[bh * (N_ + 1) + r] = r2;
            r1 += e1[r]; r2 += e2[r];
        }
    }
}

// ------------- Kernel B2: materialize exclusive vector prefix arrays ------
__global__ void __launch_bounds__(256) kernelB2()
{
    int blk = blockIdx.x;
    int bh  = blk >> 2;          // 0..31
    int gb  = blk & 3;
    int tid = threadIdx.x;
    int f   = tid & 63;
    int sub = tid >> 6;
    int g   = gb * 4 + sub;      // chunk 0..15
    int b   = bh >> 3;

    float runP = g_cstart[((bh * 16 + g) * 64 + f) * 2 + 0];
    float runN = g_cstart[((bh * 16 + g) * 64 + f) * 2 + 1];

    int r0 = g * 128;
    for (int r = r0; r < r0 + 128; ++r) {
        *(float2*)&g_cum[((size_t)bh * (N_ + 1) + r) * 128 + f * 2] = make_float2(runP, runN);
        float v  = g_V[((size_t)b * N_ + g_si[bh * N_ + r]) * 64 + f];
        float w1 = g_e1[bh * N_ + r];
        float w2 = g_e2[bh * N_ + r];
        runP += w1 * v;
        runN += w2 * v;
    }
}

// ------------- Kernel C: produce outputs ---------------------------------
__global__ void __launch_bounds__(256) kernelC(float* __restrict__ out)
{
    int blk = blockIdx.x;
    int bh  = blk >> 4;          // 0..31
    int seg = blk & 15;
    int b   = bh >> 3, h = bh & 7;
    int tid = threadIdx.x;
    int w = tid >> 5, lane = tid & 31;

    __shared__ float sTot[128];     // totals row (interleaved P,N)
    __shared__ float sE1tot;
    if (tid < 128) sTot[tid] = g_cum[((size_t)bh * (N_ + 1) + N_) * 128 + tid];
    if (tid == 128) sE1tot = g_pe1[bh * (N_ + 1) + N_];
    __syncthreads();

    float e1tot = sE1tot;
    for (int it = 0; it < 16; ++it) {
        int i = seg * 128 + w * 16 + it;
        float kv = g_K[bh * N_ + i];
        int   t  = g_t[bh * N_ + i];
        float ek  = __expf(kv);
        float ek2 = __expf(0.01f * kv);
        float pe1 = g_pe1[bh * (N_ + 1) + t];
        float pe2 = g_pe2[bh * (N_ + 1) + t];
        float denom = ek * (e1tot - pe1) + ek2 * pe2;
        float inv = 1.0f / denom;

        const float4 c = *(const float4*)&g_cum[((size_t)bh * (N_ + 1) + t) * 128 + lane * 4];
        // c = (P(f0), N(f0), P(f1), N(f1)) for f0 = 2*lane, f1 = 2*lane+1
        float o0 = (ek * (sTot[lane * 4 + 0] - c.x) + ek2 * c.y) * inv;
        float o1 = (ek * (sTot[lane * 4 + 2] - c.z) + ek2 * c.w) * inv;
        *(float2*)&out[((size_t)(b * N_ + i)) * 512 + h * 64 + lane * 2] = make_float2(o0, o1);
    }
}

// ------------- launch -----------------------------------------------------
extern "C" void kernel_launch(void* const* d_in, const int* in_sizes, int n_in,
                              void* d_out, int out_size)
{
    const float* X  = (const float*)d_in[0];
    const float* Wv = (const float*)d_in[1];
    const float* bv = (const float*)d_in[2];
    const float* Wq = (const float*)d_in[3];
    const float* bq = (const float*)d_in[4];
    const float* Wk = (const float*)d_in[5];
    const float* bk = (const float*)d_in[6];

    kernelA<<<(B_ * N_) / 64, 256>>>(X, Wv, bv, Wq, bq, Wk, bk);
    kernelB1<<<BH_, 1024>>>();
    kernelB2<<<BH_ * 4, 256>>>();
    kernelC<<<BH_ * 16, 256>>>((float*)d_out);
}

// round 3
// speedup vs baseline: 1.2539x; 1.2539x over previous
#include <cuda_runtime.h>

#define B_    4
#define N_    2048
#define INF_  512
#define D_    64
#define H_    8
#define BH_   32
#define NCHUNK 32          // 64 ranks per chunk
#define CHSZ   64

// ---------------- scratch (device globals; no allocation) ----------------
__device__ __align__(16) float g_V[B_ * N_ * D_];            // (b, n, 64)
__device__ float g_Q[BH_ * N_];                              // (b*8+h, n)
__device__ float g_K[BH_ * N_];
__device__ int   g_si[BH_ * N_];                             // sorted index
__device__ float g_e1[BH_ * N_];                             // exp(Qsorted)
__device__ float g_e2[BH_ * N_];                             // exp(0.01*Qsorted)
__device__ float g_pe1[BH_ * (N_ + 1)];                      // exclusive scalar prefix of e1
__device__ float g_pe2[BH_ * (N_ + 1)];
__device__ int   g_t[BH_ * N_];                              // rank t_i per output row
__device__ float g_cstart[BH_ * NCHUNK * 128];               // chunk-start running sums, col=2f+pn
__device__ float g_tot[BH_ * 128];                           // column totals (interleaved P,N)
__device__ int   g_bcnt[BH_ * NCHUNK];                       // bucket counts
__device__ int   g_blist[BH_ * NCHUNK * N_];                 // bucket member lists

// ---------------- Kernel A: V = X@Wv + bv, then Q,K projections ----------
__global__ void __launch_bounds__(256) kernelA(
    const float* __restrict__ X,  const float* __restrict__ Wv, const float* __restrict__ bv,
    const float* __restrict__ Wq, const float* __restrict__ bq,
    const float* __restrict__ Wk, const float* __restrict__ bk)
{
    __shared__ float Xs[64][33];
    __shared__ __align__(16) float Ws[32][64];
    __shared__ float Vs[64][65];

    int tid = threadIdx.x;
    int tx = tid & 15, ty = tid >> 4;
    int row0 = blockIdx.x * 64;                 // global row over b*N_

    float acc[4][4] = {};

    for (int kt = 0; kt < INF_; kt += 32) {
        for (int idx = tid; idx < 64 * 32; idx += 256) {
            int r = idx >> 5, kk = idx & 31;
            Xs[r][kk] = X[(size_t)(row0 + r) * INF_ + kt + kk];
        }
        for (int idx = tid; idx < 32 * 64; idx += 256) {
            int kk = idx >> 6, c = idx & 63;
            Ws[kk][c] = Wv[(kt + kk) * 64 + c];
        }
        __syncthreads();
#pragma unroll
        for (int kk = 0; kk < 32; ++kk) {
            float a0 = Xs[ty * 4 + 0][kk];
            float a1 = Xs[ty * 4 + 1][kk];
            float a2 = Xs[ty * 4 + 2][kk];
            float a3 = Xs[ty * 4 + 3][kk];
            float4 bb = *(const float4*)&Ws[kk][tx * 4];
            acc[0][0] += a0 * bb.x; acc[0][1] += a0 * bb.y; acc[0][2] += a0 * bb.z; acc[0][3] += a0 * bb.w;
            acc[1][0] += a1 * bb.x; acc[1][1] += a1 * bb.y; acc[1][2] += a1 * bb.z; acc[1][3] += a1 * bb.w;
            acc[2][0] += a2 * bb.x; acc[2][1] += a2 * bb.y; acc[2][2] += a2 * bb.z; acc[2][3] += a2 * bb.w;
            acc[3][0] += a3 * bb.x; acc[3][1] += a3 * bb.y; acc[3][2] += a3 * bb.z; acc[3][3] += a3 * bb.w;
        }
        __syncthreads();
    }

    float b0 = bv[tx * 4 + 0], b1 = bv[tx * 4 + 1], b2 = bv[tx * 4 + 2], b3 = bv[tx * 4 + 3];
#pragma unroll
    for (int i = 0; i < 4; ++i) {
        Vs[ty * 4 + i][tx * 4 + 0] = acc[i][0] + b0;
        Vs[ty * 4 + i][tx * 4 + 1] = acc[i][1] + b1;
        Vs[ty * 4 + i][tx * 4 + 2] = acc[i][2] + b2;
        Vs[ty * 4 + i][tx * 4 + 3] = acc[i][3] + b3;
    }
    __syncthreads();

    // write V
#pragma unroll
    for (int i = 0; i < 4; ++i) {
        float4 v = make_float4(Vs[ty * 4 + i][tx * 4 + 0], Vs[ty * 4 + i][tx * 4 + 1],
                               Vs[ty * 4 + i][tx * 4 + 2], Vs[ty * 4 + i][tx * 4 + 3]);
        *(float4*)&g_V[(size_t)(row0 + ty * 4 + i) * 64 + tx * 4] = v;
    }

    // Q, K projections: 64 rows x 8 heads; each thread does 2 heads of 1 row
    int bb_ = row0 >> 11;               // batch
    int n0  = row0 & (N_ - 1);
    int r   = tid >> 2;
    int hp  = (tid & 3) * 2;
    float q0 = bq[hp], q1 = bq[hp + 1];
    float k0 = bk[hp], k1 = bk[hp + 1];
#pragma unroll 8
    for (int f = 0; f < 64; ++f) {
        float v = Vs[r][f];
        q0 += v * Wq[f * 8 + hp]; q1 += v * Wq[f * 8 + hp + 1];
        k0 += v * Wk[f * 8 + hp]; k1 += v * Wk[f * 8 + hp + 1];
    }
    int n = n0 + r;
    g_Q[(bb_ * 8 + hp) * N_ + n]     = q0;
    g_Q[(bb_ * 8 + hp + 1) * N_ + n] = q1;
    g_K[(bb_ * 8 + hp) * N_ + n]     = k0;
    g_K[(bb_ * 8 + hp + 1) * N_ + n] = k1;
}

// ------------- Kernel B1: STABLE radix sort + scans + ranks + buckets -----
// dynamic smem layout (elements):
//   key[2048] idx[2048] key2[2048] idx2[2048] e1[2048] e2[2048]
//   partP[32*64] partN[32*64] cnt[1024] wsum[32] c1[128] c2[128] bcnt[32]
#define B1_SMEM_BYTES ((8 * 2048 + 1024 + 32 + 128 + 128 + 32) * 4)

__device__ __forceinline__ unsigned f2u_order(float f) {
    unsigned u = __float_as_uint(f);
    return u ^ ((u >> 31) ? 0xFFFFFFFFu : 0x80000000u);
}

__global__ void __launch_bounds__(1024) kernelB1()
{
    extern __shared__ __align__(16) char smemRaw[];
    unsigned* key   = (unsigned*)smemRaw;
    int*      idx   = (int*)(key + 2048);
    unsigned* key2  = (unsigned*)(idx + 2048);
    int*      idx2  = (int*)(key2 + 2048);
    float*    e1    = (float*)(idx2 + 2048);
    float*    e2    = e1 + 2048;
    float*    partP = e2 + 2048;              // [32][64]
    float*    partN = partP + 2048;
    int*      cnt   = (int*)(partN + 2048);   // [16][64] digit-major
    int*      wsum  = cnt + 1024;             // 32
    float*    c1    = (float*)(wsum + 32);    // 128
    float*    c2    = c1 + 128;
    int*      bcnt  = (int*)(c2 + 128);       // 32

    int bh = blockIdx.x;
    int b  = bh >> 3;
    int tid = threadIdx.x;
    int lane = tid & 31;
    unsigned ltmask = (lane == 0) ? 0u : (0xFFFFFFFFu >> (32 - lane));

    // load + order-preserving transform
    for (int r = tid; r < N_; r += 1024) {
        key[r] = f2u_order(g_Q[bh * N_ + r]);
        idx[r] = r;
    }
    __syncthreads();

    // STABLE 4-bit LSD radix sort, 8 passes.
    // Logical warps: positions 0..1023 -> lw 0..31 (this thread's elem0),
    //                positions 1024..2047 -> lw 32..63 (elem1).
    unsigned* kin = key;  unsigned* kout = key2;
    int*      iin = idx;  int*      iout = idx2;
    int lw0 = tid >> 5, lw1 = 32 + (tid >> 5);
#pragma unroll
    for (int pass = 0; pass < 8; ++pass) {
        int shift = pass * 4;
        cnt[tid] = 0;
        __syncthreads();

        unsigned k0 = kin[tid], k1 = kin[tid + 1024];
        int      i0 = iin[tid], i1 = iin[tid + 1024];
        int d0 = (k0 >> shift) & 15, d1 = (k1 >> shift) & 15;

        unsigned m0 = __match_any_sync(0xFFFFFFFFu, d0);
        unsigned m1 = __match_any_sync(0xFFFFFFFFu, d1);
        int r0 = __popc(m0 & ltmask);
        int r1 = __popc(m1 & ltmask);
        if (r0 == 0) cnt[d0 * 64 + lw0] = __popc(m0);
        if (r1 == 0) cnt[d1 * 64 + lw1] = __popc(m1);
        __syncthreads();

        // block exclusive scan of cnt[1024] (digit-major -> stable global offsets)
        int v = cnt[tid];
        int inc = v;
#pragma unroll
        for (int off = 1; off < 32; off <<= 1) {
            int nn = __shfl_up_sync(0xFFFFFFFFu, inc, off);
            if (lane >= off) inc += nn;
        }
        if (lane == 31) wsum[tid >> 5] = inc;
        __syncthreads();
        if (tid < 32) {
            int wv = wsum[tid];
            int winc = wv;
#pragma unroll
            for (int off = 1; off < 32; off <<= 1) {
                int nn = __shfl_up_sync(0xFFFFFFFFu, winc, off);
                if (tid >= off) winc += nn;
            }
            wsum[tid] = winc - wv;   // exclusive
        }
        __syncthreads();
        cnt[tid] = inc - v + wsum[tid >> 5];   // exclusive global offset
        __syncthreads();

        int p0 = cnt[d0 * 64 + lw0] + r0;
        int p1 = cnt[d1 * 64 + lw1] + r1;
        kout[p0] = k0; iout[p0] = i0;
        kout[p1] = k1; iout[p1] = i1;
        __syncthreads();
        unsigned* tk = kin; kin = kout; kout = tk;
        int*      ti = iin; iin = iout; iout = ti;
    }
    // after 8 passes sorted data is back in key / idx

    // exp tables + publish sorted order
    for (int r = tid; r < N_; r += 1024) {
        unsigned u = key[r];
        float q = __uint_as_float(u ^ ((u >> 31) ? 0x80000000u : 0xFFFFFFFFu));
        float x1 = __expf(q), x2 = __expf(0.01f * q);
        e1[r] = x1; e2[r] = x2;
        g_si[bh * N_ + r] = idx[r];
        g_e1[bh * N_ + r] = x1;
        g_e2[bh * N_ + r] = x2;
    }
    if (tid < NCHUNK) bcnt[tid] = 0;
    __syncthreads();

    // ranks (binary search in uint key domain) + chunk buckets
    for (int i = tid; i < N_; i += 1024) {
        unsigned tu = f2u_order(-g_K[bh * N_ + i]);
        int lo = 0, hi = N_;
        while (lo < hi) {
            int mid = (lo + hi) >> 1;
            if (key[mid] <= tu) lo = mid + 1; else hi = mid;
        }
        g_t[bh * N_ + i] = lo;
        int c = lo >> 6; if (c > NCHUNK - 1) c = NCHUNK - 1;   // t==2048 -> chunk 31
        int pos = atomicAdd(&bcnt[c], 1);
        g_blist[(bh * NCHUNK + c) * N_ + pos] = i;
    }

    // chunk partial vector sums (each (g,f) thread covers chunks 2g and 2g+1)
    {
        int f = tid & 63, g = tid >> 6;          // g: 0..15
        int r0 = g * 128;
        float aP = 0.f, aN = 0.f;
        for (int r = r0; r < r0 + 64; ++r) {
            float v = g_V[((size_t)b * N_ + idx[r]) * 64 + f];
            aP += e1[r] * v; aN += e2[r] * v;
        }
        partP[(2 * g) * 64 + f] = aP; partN[(2 * g) * 64 + f] = aN;
        float bP = 0.f, bN = 0.f;
        for (int r = r0 + 64; r < r0 + 128; ++r) {
            float v = g_V[((size_t)b * N_ + idx[r]) * 64 + f];
            bP += e1[r] * v; bN += e2[r] * v;
        }
        partP[(2 * g + 1) * 64 + f] = bP; partN[(2 * g + 1) * 64 + f] = bN;
    }
    __syncthreads();

    // exclusive scan over chunks -> g_cstart, totals -> g_tot
    if (tid < 64) {
        float run = 0.f;
        for (int gg = 0; gg < NCHUNK; ++gg) {
            float t = partP[gg * 64 + tid];
            g_cstart[(bh * NCHUNK + gg) * 128 + 2 * tid] = run;
            run += t;
        }
        g_tot[bh * 128 + 2 * tid] = run;
    } else if (tid < 128) {
        int ff = tid - 64;
        float run = 0.f;
        for (int gg = 0; gg < NCHUNK; ++gg) {
            float t = partN[gg * 64 + ff];
            g_cstart[(bh * NCHUNK + gg) * 128 + 2 * ff + 1] = run;
            run += t;
        }
        g_tot[bh * 128 + 2 * ff + 1] = run;
    }

    // scalar exclusive scans of e1, e2
    if (tid < 128) {
        float s1 = 0.f, s2 = 0.f;
        for (int q = 0; q < 16; ++q) { s1 += e1[tid * 16 + q]; s2 += e2[tid * 16 + q]; }
        c1[tid] = s1; c2[tid] = s2;
    }
    __syncthreads();
    if (tid == 0) {
        float r1 = 0.f, r2 = 0.f;
        for (int q = 0; q < 128; ++q) {
            float t1 = c1[q], t2 = c2[q];
            c1[q] = r1; c2[q] = r2;
            r1 += t1; r2 += t2;
        }
        g_pe1[bh * (N_ + 1) + N_] = r1;
        g_pe2[bh * (N_ + 1) + N_] = r2;
    }
    __syncthreads();
    if (tid < 128) {
        float r1 = c1[tid], r2 = c2[tid];
        for (int q = 0; q < 16; ++q) {
            int r = tid * 16 + q;
            g_pe1[bh * (N_ + 1) + r] = r1;
            g_pe2[bh * (N_ + 1) + r] = r2;
            r1 += e1[r]; r2 += e2[r];
        }
    }
    if (tid < NCHUNK) g_bcnt[bh * NCHUNK + tid] = bcnt[tid];
}

// ------------- Kernel BC: per-chunk smem prefix + direct output ----------
__global__ void __launch_bounds__(256) kernelBC(float* __restrict__ out)
{
    __shared__ __align__(16) float contrib[CHSZ * 128];  // 64 ranks x 128 cols (P,N interleaved)
    __shared__ __align__(16) float colEnd[128];
    __shared__ __align__(16) float sTot[128];
    __shared__ float e1s[CHSZ], e2s[CHSZ];
    __shared__ int   sidx[CHSZ];
    __shared__ float sE1tot;

    int blk = blockIdx.x;
    int bh  = blk >> 5;          // 0..31
    int g   = blk & 31;          // chunk
    int b   = bh >> 3, h = bh & 7;
    int tid = threadIdx.x;
    int r0  = g * CHSZ;

    if (tid < CHSZ) {
        e1s[tid]  = g_e1[bh * N_ + r0 + tid];
        e2s[tid]  = g_e2[bh * N_ + r0 + tid];
        sidx[tid] = g_si[bh * N_ + r0 + tid];
    }
    if (tid >= 128 && tid < 256) sTot[tid - 128] = g_tot[bh * 128 + tid - 128];
    if (tid == 64) sE1tot = g_pe1[bh * (N_ + 1) + N_];
    __syncthreads();

    // gather weighted V rows: 64 rows x 64 f
    for (int id = tid; id < CHSZ * 64; id += 256) {
        int r = id >> 6, f = id & 63;
        float v = g_V[((size_t)b * N_ + sidx[r]) * 64 + f];
        *(float2*)&contrib[r * 128 + 2 * f] = make_float2(e1s[r] * v, e2s[r] * v);
    }
    __syncthreads();

    // in-place exclusive scan along ranks, one column per thread (128 cols)
    if (tid < 128) {
        float run = g_cstart[(bh * NCHUNK + g) * 128 + tid];
#pragma unroll 8
        for (int r = 0; r < CHSZ; ++r) {
            float t = contrib[r * 128 + tid];
            contrib[r * 128 + tid] = run;
            run += t;
        }
        colEnd[tid] = run;
    }
    __syncthreads();

    // outputs: one warp per row i
    int cnt  = g_bcnt[bh * NCHUNK + g];
    int w    = tid >> 5, lane = tid & 31;
    float e1tot = sE1tot;
    for (int ii = w; ii < cnt; ii += 8) {
        int   i  = g_blist[(bh * NCHUNK + g) * N_ + ii];
        int   t  = g_t[bh * N_ + i];
        int   local = t - r0;
        float kv = g_K[bh * N_ + i];
        float ek  = __expf(kv);
        float ek2 = __expf(0.01f * kv);
        float pe1 = g_pe1[bh * (N_ + 1) + t];
        float pe2 = g_pe2[bh * (N_ + 1) + t];
        float denom = ek * (e1tot - pe1) + ek2 * pe2;
        float inv = 1.0f / denom;

        const float* row = (local < CHSZ) ? &contrib[local * 128] : colEnd;
        float4 c = *(const float4*)&row[lane * 4];
        float o0 = (ek * (sTot[lane * 4 + 0] - c.x) + ek2 * c.y) * inv;
        float o1 = (ek * (sTot[lane * 4 + 2] - c.z) + ek2 * c.w) * inv;
        *(float2*)&out[((size_t)(b * N_ + i)) * 512 + h * 64 + lane * 2] = make_float2(o0, o1);
    }
}

// ------------- launch -----------------------------------------------------
extern "C" void kernel_launch(void* const* d_in, const int* in_sizes, int n_in,
                              void* d_out, int out_size)
{
    const float* X  = (const float*)d_in[0];
    const float* Wv = (const float*)d_in[1];
    const float* bv = (const float*)d_in[2];
    const float* Wq = (const float*)d_in[3];
    const float* bq = (const float*)d_in[4];
    const float* Wk = (const float*)d_in[5];
    const float* bk = (const float*)d_in[6];

    cudaFuncSetAttribute(kernelB1, cudaFuncAttributeMaxDynamicSharedMemorySize, B1_SMEM_BYTES);

    kernelA<<<(B_ * N_) / 64, 256>>>(X, Wv, bv, Wq, bq, Wk, bk);
    kernelB1<<<BH_, 1024, B1_SMEM_BYTES>>>();
    kernelBC<<<BH_ * NCHUNK, 256>>>((float*)d_out);
}

// round 4
// speedup vs baseline: 1.4444x; 1.1520x over previous
#include <cuda_runtime.h>

#define B_    4
#define N_    2048
#define INF_  512
#define D_    64
#define H_    8
#define BH_   32
#define NCHUNK 32          // 64 ranks per chunk
#define CHSZ   64

// ---------------- scratch (device globals; no allocation) ----------------
__device__ __align__(16) float g_V[B_ * N_ * D_];            // (b, n, 64)
__device__ float g_Q[BH_ * N_];                              // (b*8+h, n)
__device__ float g_K[BH_ * N_];
__device__ int   g_si[BH_ * N_];                             // sorted index
__device__ float g_e1[BH_ * N_];                             // exp(Qsorted)
__device__ float g_e2[BH_ * N_];                             // exp(0.01*Qsorted)
__device__ float g_pe1[BH_ * (N_ + 1)];                      // exclusive scalar prefix of e1
__device__ float g_pe2[BH_ * (N_ + 1)];
__device__ int   g_t[BH_ * N_];                              // rank t_i per output row
__device__ float g_cstart[BH_ * NCHUNK * 128];               // chunk-start running sums, col=2f+pn
__device__ float g_tot[BH_ * 128];                           // column totals (interleaved P,N)
__device__ int   g_bcnt[BH_ * NCHUNK];                       // bucket counts
__device__ int   g_blist[BH_ * NCHUNK * N_];                 // bucket member lists

// ---------------- Kernel A: pipelined V = X@Wv + bv, then Q,K projections
__global__ void __launch_bounds__(256) kernelA(
    const float* __restrict__ X,  const float* __restrict__ Wv, const float* __restrict__ bv,
    const float* __restrict__ Wq, const float* __restrict__ bq,
    const float* __restrict__ Wk, const float* __restrict__ bk)
{
    __shared__ __align__(16) float XsT[2][32][68];   // transposed: [buf][k][row]
    __shared__ __align__(16) float Ws[2][32][64];    // [buf][k][col]
    __shared__ __align__(16) float Vs[64][65];

    int tid = threadIdx.x;
    int tx = tid & 15, ty = tid >> 4;
    int row0 = blockIdx.x * 64;                 // global row over b*N_

    // decode load assignments once
    int xi0 = tid,        xi1 = tid + 256;      // 512 float4 X elems per ktile
    int xr0 = xi0 >> 3,   xk0 = xi0 & 7;
    int xr1 = xi1 >> 3,   xk1 = xi1 & 7;
    int wk0 = xi0 >> 4,   wc0 = xi0 & 15;       // 512 float4 W elems per ktile
    int wk1 = xi1 >> 4,   wc1 = xi1 & 15;

    const float* Xr0 = X + (size_t)(row0 + xr0) * INF_ + xk0 * 4;
    const float* Xr1 = X + (size_t)(row0 + xr1) * INF_ + xk1 * 4;

    float4 xa, xb, wa, wb;
    // prologue: load ktile 0
    xa = *(const float4*)(Xr0);
    xb = *(const float4*)(Xr1);
    wa = *(const float4*)&Wv[wk0 * 64 + wc0 * 4];
    wb = *(const float4*)&Wv[wk1 * 64 + wc1 * 4];
    XsT[0][xk0 * 4 + 0][xr0] = xa.x; XsT[0][xk0 * 4 + 1][xr0] = xa.y;
    XsT[0][xk0 * 4 + 2][xr0] = xa.z; XsT[0][xk0 * 4 + 3][xr0] = xa.w;
    XsT[0][xk1 * 4 + 0][xr1] = xb.x; XsT[0][xk1 * 4 + 1][xr1] = xb.y;
    XsT[0][xk1 * 4 + 2][xr1] = xb.z; XsT[0][xk1 * 4 + 3][xr1] = xb.w;
    *(float4*)&Ws[0][wk0][wc0 * 4] = wa;
    *(float4*)&Ws[0][wk1][wc1 * 4] = wb;
    __syncthreads();

    float acc[4][4] = {};

#pragma unroll 1
    for (int kt = 0; kt < 16; ++kt) {
        int p = kt & 1;
        if (kt < 15) {
            int o = (kt + 1) * 32;
            xa = *(const float4*)(Xr0 + o);
            xb = *(const float4*)(Xr1 + o);
            wa = *(const float4*)&Wv[(o + wk0) * 64 + wc0 * 4];
            wb = *(const float4*)&Wv[(o + wk1) * 64 + wc1 * 4];
        }
#pragma unroll
        for (int kk = 0; kk < 32; ++kk) {
            float4 av = *(const float4*)&XsT[p][kk][ty * 4];
            float4 bw = *(const float4*)&Ws[p][kk][tx * 4];
            acc[0][0] += av.x * bw.x; acc[0][1] += av.x * bw.y; acc[0][2] += av.x * bw.z; acc[0][3] += av.x * bw.w;
            acc[1][0] += av.y * bw.x; acc[1][1] += av.y * bw.y; acc[1][2] += av.y * bw.z; acc[1][3] += av.y * bw.w;
            acc[2][0] += av.z * bw.x; acc[2][1] += av.z * bw.y; acc[2][2] += av.z * bw.z; acc[2][3] += av.z * bw.w;
            acc[3][0] += av.w * bw.x; acc[3][1] += av.w * bw.y; acc[3][2] += av.w * bw.z; acc[3][3] += av.w * bw.w;
        }
        if (kt < 15) {
            int np = p ^ 1;
            XsT[np][xk0 * 4 + 0][xr0] = xa.x; XsT[np][xk0 * 4 + 1][xr0] = xa.y;
            XsT[np][xk0 * 4 + 2][xr0] = xa.z; XsT[np][xk0 * 4 + 3][xr0] = xa.w;
            XsT[np][xk1 * 4 + 0][xr1] = xb.x; XsT[np][xk1 * 4 + 1][xr1] = xb.y;
            XsT[np][xk1 * 4 + 2][xr1] = xb.z; XsT[np][xk1 * 4 + 3][xr1] = xb.w;
            *(float4*)&Ws[np][wk0][wc0 * 4] = wa;
            *(float4*)&Ws[np][wk1][wc1 * 4] = wb;
            __syncthreads();
        }
    }

    float b0 = bv[tx * 4 + 0], b1 = bv[tx * 4 + 1], b2 = bv[tx * 4 + 2], b3 = bv[tx * 4 + 3];
#pragma unroll
    for (int i = 0; i < 4; ++i) {
        Vs[ty * 4 + i][tx * 4 + 0] = acc[i][0] + b0;
        Vs[ty * 4 + i][tx * 4 + 1] = acc[i][1] + b1;
        Vs[ty * 4 + i][tx * 4 + 2] = acc[i][2] + b2;
        Vs[ty * 4 + i][tx * 4 + 3] = acc[i][3] + b3;
    }
    __syncthreads();

    // write V
#pragma unroll
    for (int i = 0; i < 4; ++i) {
        float4 v = make_float4(Vs[ty * 4 + i][tx * 4 + 0], Vs[ty * 4 + i][tx * 4 + 1],
                               Vs[ty * 4 + i][tx * 4 + 2], Vs[ty * 4 + i][tx * 4 + 3]);
        *(float4*)&g_V[(size_t)(row0 + ty * 4 + i) * 64 + tx * 4] = v;
    }

    // Q, K projections: 64 rows x 8 heads; each thread does 2 heads of 1 row
    int bb_ = row0 >> 11;               // batch
    int n0  = row0 & (N_ - 1);
    int r   = tid >> 2;
    int hp  = (tid & 3) * 2;
    float q0 = bq[hp], q1 = bq[hp + 1];
    float k0 = bk[hp], k1 = bk[hp + 1];
#pragma unroll 8
    for (int f = 0; f < 64; ++f) {
        float v = Vs[r][f];
        q0 += v * Wq[f * 8 + hp]; q1 += v * Wq[f * 8 + hp + 1];
        k0 += v * Wk[f * 8 + hp]; k1 += v * Wk[f * 8 + hp + 1];
    }
    int n = n0 + r;
    g_Q[(bb_ * 8 + hp) * N_ + n]     = q0;
    g_Q[(bb_ * 8 + hp + 1) * N_ + n] = q1;
    g_K[(bb_ * 8 + hp) * N_ + n]     = k0;
    g_K[(bb_ * 8 + hp + 1) * N_ + n] = k1;
}

// ------------- Kernel B1: STABLE radix sort + scans + ranks + buckets -----
// dynamic smem layout (elements):
//   key[2048] idx[2048] key2[2048] idx2[2048] e1[2048] e2[2048]
//   partP[32*64] partN[32*64] cnt[1024] wsum[32] c1[128] c2[128] bcnt[32]
#define B1_SMEM_BYTES ((8 * 2048 + 1024 + 32 + 128 + 128 + 32) * 4)

__device__ __forceinline__ unsigned f2u_order(float f) {
    unsigned u = __float_as_uint(f);
    return u ^ ((u >> 31) ? 0xFFFFFFFFu : 0x80000000u);
}

__global__ void __launch_bounds__(1024) kernelB1()
{
    extern __shared__ __align__(16) char smemRaw[];
    unsigned* key   = (unsigned*)smemRaw;
    int*      idx   = (int*)(key + 2048);
    unsigned* key2  = (unsigned*)(idx + 2048);
    int*      idx2  = (int*)(key2 + 2048);
    float*    e1    = (float*)(idx2 + 2048);
    float*    e2    = e1 + 2048;
    float*    partP = e2 + 2048;              // [32][64]
    float*    partN = partP + 2048;
    int*      cnt   = (int*)(partN + 2048);   // [16][64] digit-major
    int*      wsum  = cnt + 1024;             // 32
    float*    c1    = (float*)(wsum + 32);    // 128
    float*    c2    = c1 + 128;
    int*      bcnt  = (int*)(c2 + 128);       // 32

    int bh = blockIdx.x;
    int b  = bh >> 3;
    int tid = threadIdx.x;
    int lane = tid & 31;
    unsigned ltmask = (lane == 0) ? 0u : (0xFFFFFFFFu >> (32 - lane));

    // load + order-preserving transform
    for (int r = tid; r < N_; r += 1024) {
        key[r] = f2u_order(g_Q[bh * N_ + r]);
        idx[r] = r;
    }
    __syncthreads();

    // STABLE 4-bit LSD radix sort, 8 passes.
    unsigned* kin = key;  unsigned* kout = key2;
    int*      iin = idx;  int*      iout = idx2;
    int lw0 = tid >> 5, lw1 = 32 + (tid >> 5);
#pragma unroll
    for (int pass = 0; pass < 8; ++pass) {
        int shift = pass * 4;
        cnt[tid] = 0;
        __syncthreads();

        unsigned k0 = kin[tid], k1 = kin[tid + 1024];
        int      i0 = iin[tid], i1 = iin[tid + 1024];
        int d0 = (k0 >> shift) & 15, d1 = (k1 >> shift) & 15;

        unsigned m0 = __match_any_sync(0xFFFFFFFFu, d0);
        unsigned m1 = __match_any_sync(0xFFFFFFFFu, d1);
        int r0 = __popc(m0 & ltmask);
        int r1 = __popc(m1 & ltmask);
        if (r0 == 0) cnt[d0 * 64 + lw0] = __popc(m0);
        if (r1 == 0) cnt[d1 * 64 + lw1] = __popc(m1);
        __syncthreads();

        // block exclusive scan of cnt[1024]
        int v = cnt[tid];
        int inc = v;
#pragma unroll
        for (int off = 1; off < 32; off <<= 1) {
            int nn = __shfl_up_sync(0xFFFFFFFFu, inc, off);
            if (lane >= off) inc += nn;
        }
        if (lane == 31) wsum[tid >> 5] = inc;
        __syncthreads();
        if (tid < 32) {
            int wv = wsum[tid];
            int winc = wv;
#pragma unroll
            for (int off = 1; off < 32; off <<= 1) {
                int nn = __shfl_up_sync(0xFFFFFFFFu, winc, off);
                if (tid >= off) winc += nn;
            }
            wsum[tid] = winc - wv;   // exclusive
        }
        __syncthreads();
        cnt[tid] = inc - v + wsum[tid >> 5];   // exclusive global offset
        __syncthreads();

        int p0 = cnt[d0 * 64 + lw0] + r0;
        int p1 = cnt[d1 * 64 + lw1] + r1;
        kout[p0] = k0; iout[p0] = i0;
        kout[p1] = k1; iout[p1] = i1;
        __syncthreads();
        unsigned* tk = kin; kin = kout; kout = tk;
        int*      ti = iin; iin = iout; iout = ti;
    }

    // exp tables + publish sorted order
    for (int r = tid; r < N_; r += 1024) {
        unsigned u = key[r];
        float q = __uint_as_float(u ^ ((u >> 31) ? 0x80000000u : 0xFFFFFFFFu));
        float x1 = __expf(q), x2 = __expf(0.01f * q);
        e1[r] = x1; e2[r] = x2;
        g_si[bh * N_ + r] = idx[r];
        g_e1[bh * N_ + r] = x1;
        g_e2[bh * N_ + r] = x2;
    }
    if (tid < NCHUNK) bcnt[tid] = 0;
    __syncthreads();

    // ranks (binary search in uint key domain) + chunk buckets
    for (int i = tid; i < N_; i += 1024) {
        unsigned tu = f2u_order(-g_K[bh * N_ + i]);
        int lo = 0, hi = N_;
        while (lo < hi) {
            int mid = (lo + hi) >> 1;
            if (key[mid] <= tu) lo = mid + 1; else hi = mid;
        }
        g_t[bh * N_ + i] = lo;
        int c = lo >> 6; if (c > NCHUNK - 1) c = NCHUNK - 1;   // t==2048 -> chunk 31
        int pos = atomicAdd(&bcnt[c], 1);
        g_blist[(bh * NCHUNK + c) * N_ + pos] = i;
    }

    // chunk partial vector sums
    {
        int f = tid & 63, g = tid >> 6;          // g: 0..15
        int r0 = g * 128;
        float aP = 0.f, aN = 0.f;
        for (int r = r0; r < r0 + 64; ++r) {
            float v = g_V[((size_t)b * N_ + idx[r]) * 64 + f];
            aP += e1[r] * v; aN += e2[r] * v;
        }
        partP[(2 * g) * 64 + f] = aP; partN[(2 * g) * 64 + f] = aN;
        float bP = 0.f, bN = 0.f;
        for (int r = r0 + 64; r < r0 + 128; ++r) {
            float v = g_V[((size_t)b * N_ + idx[r]) * 64 + f];
            bP += e1[r] * v; bN += e2[r] * v;
        }
        partP[(2 * g + 1) * 64 + f] = bP; partN[(2 * g + 1) * 64 + f] = bN;
    }
    __syncthreads();

    // exclusive scan over chunks -> g_cstart, totals -> g_tot
    if (tid < 64) {
        float run = 0.f;
        for (int gg = 0; gg < NCHUNK; ++gg) {
            float t = partP[gg * 64 + tid];
            g_cstart[(bh * NCHUNK + gg) * 128 + 2 * tid] = run;
            run += t;
        }
        g_tot[bh * 128 + 2 * tid] = run;
    } else if (tid < 128) {
        int ff = tid - 64;
        float run = 0.f;
        for (int gg = 0; gg < NCHUNK; ++gg) {
            float t = partN[gg * 64 + ff];
            g_cstart[(bh * NCHUNK + gg) * 128 + 2 * ff + 1] = run;
            run += t;
        }
        g_tot[bh * 128 + 2 * ff + 1] = run;
    }

    // scalar exclusive scans of e1, e2
    if (tid < 128) {
        float s1 = 0.f, s2 = 0.f;
        for (int q = 0; q < 16; ++q) { s1 += e1[tid * 16 + q]; s2 += e2[tid * 16 + q]; }
        c1[tid] = s1; c2[tid] = s2;
    }
    __syncthreads();
    if (tid == 0) {
        float r1 = 0.f, r2 = 0.f;
        for (int q = 0; q < 128; ++q) {
            float t1 = c1[q], t2 = c2[q];
            c1[q] = r1; c2[q] = r2;
            r1 += t1; r2 += t2;
        }
        g_pe1[bh * (N_ + 1) + N_] = r1;
        g_pe2[bh * (N_ + 1) + N_] = r2;
    }
    __syncthreads();
    if (tid < 128) {
        float r1 = c1[tid], r2 = c2[tid];
        for (int q = 0; q < 16; ++q) {
            int r = tid * 16 + q;
            g_pe1[bh * (N_ + 1) + r] = r1;
            g_pe2[bh * (N_ + 1) + r] = r2;
            r1 += e1[r]; r2 += e2[r];
        }
    }
    if (tid < NCHUNK) g_bcnt[bh * NCHUNK + tid] = bcnt[tid];
}

// ------------- Kernel BC: per-chunk smem prefix + direct output ----------
__global__ void __launch_bounds__(256) kernelBC(float* __restrict__ out)
{
    __shared__ __align__(16) float contrib[CHSZ * 128];  // 64 ranks x 128 cols (P,N interleaved)
    __shared__ __align__(16) float colEnd[128];
    __shared__ __align__(16) float sTot[128];
    __shared__ float e1s[CHSZ], e2s[CHSZ];
    __shared__ int   sidx[CHSZ];
    __shared__ float sE1tot;

    int blk = blockIdx.x;
    int bh  = blk >> 5;          // 0..31
    int g   = blk & 31;          // chunk
    int b   = bh >> 3, h = bh & 7;
    int tid = threadIdx.x;
    int r0  = g * CHSZ;

    if (tid < CHSZ) {
        e1s[tid]  = g_e1[bh * N_ + r0 + tid];
        e2s[tid]  = g_e2[bh * N_ + r0 + tid];
        sidx[tid] = g_si[bh * N_ + r0 + tid];
    }
    if (tid >= 128 && tid < 256) sTot[tid - 128] = g_tot[bh * 128 + tid - 128];
    if (tid == 64) sE1tot = g_pe1[bh * (N_ + 1) + N_];
    __syncthreads();

    // gather weighted V rows: 64 rows x 64 f
    for (int id = tid; id < CHSZ * 64; id += 256) {
        int r = id >> 6, f = id & 63;
        float v = g_V[((size_t)b * N_ + sidx[r]) * 64 + f];
        *(float2*)&contrib[r * 128 + 2 * f] = make_float2(e1s[r] * v, e2s[r] * v);
    }
    __syncthreads();

    // in-place exclusive scan along ranks, one column per thread (128 cols)
    if (tid < 128) {
        float run = g_cstart[(bh * NCHUNK + g) * 128 + tid];
#pragma unroll 8
        for (int r = 0; r < CHSZ; ++r) {
            float t = contrib[r * 128 + tid];
            contrib[r * 128 + tid] = run;
            run += t;
        }
        colEnd[tid] = run;
    }
    __syncthreads();

    // outputs: one warp per row i
    int cnt  = g_bcnt[bh * NCHUNK + g];
    int w    = tid >> 5, lane = tid & 31;
    float e1tot = sE1tot;
    for (int ii = w; ii < cnt; ii += 8) {
        int   i  = g_blist[(bh * NCHUNK + g) * N_ + ii];
        int   t  = g_t[bh * N_ + i];
        int   local = t - r0;
        float kv = g_K[bh * N_ + i];
        float ek  = __expf(kv);
        float ek2 = __expf(0.01f * kv);
        float pe1 = g_pe1[bh * (N_ + 1) + t];
        float pe2 = g_pe2[bh * (N_ + 1) + t];
        float denom = ek * (e1tot - pe1) + ek2 * pe2;
        float inv = 1.0f / denom;

        const float* row = (local < CHSZ) ? &contrib[local * 128] : colEnd;
        float4 c = *(const float4*)&row[lane * 4];
        float o0 = (ek * (sTot[lane * 4 + 0] - c.x) + ek2 * c.y) * inv;
        float o1 = (ek * (sTot[lane * 4 + 2] - c.z) + ek2 * c.w) * inv;
        *(float2*)&out[((size_t)(b * N_ + i)) * 512 + h * 64 + lane * 2] = make_float2(o0, o1);
    }
}

// ------------- launch -----------------------------------------------------
extern "C" void kernel_launch(void* const* d_in, const int* in_sizes, int n_in,
                              void* d_out, int out_size)
{
    const float* X  = (const float*)d_in[0];
    const float* Wv = (const float*)d_in[1];
    const float* bv = (const float*)d_in[2];
    const float* Wq = (const float*)d_in[3];
    const float* bq = (const float*)d_in[4];
    const float* Wk = (const float*)d_in[5];
    const float* bk = (const float*)d_in[6];

    cudaFuncSetAttribute(kernelB1, cudaFuncAttributeMaxDynamicSharedMemorySize, B1_SMEM_BYTES);

    kernelA<<<(B_ * N_) / 64, 256>>>(X, Wv, bv, Wq, bq, Wk, bk);
    kernelB1<<<BH_, 1024, B1_SMEM_BYTES>>>();
    kernelBC<<<BH_ * NCHUNK, 256>>>((float*)d_out);
}